// round 13
// baseline (speedup 1.0000x reference)
#include <cuda_runtime.h>
#include <cuda_bf16.h>
#include <math.h>
#include <stdint.h>

#define BB 16
#define DKK 512
#define NN 1024
#define MMM 1024

// ---------------- scratch (device globals) ----------------
__device__ float g_scores[(size_t)BB * NN * MMM];
__device__ __nv_bfloat16 g_shi[(size_t)BB * NN * DKK];
__device__ __nv_bfloat16 g_slo[(size_t)BB * NN * DKK];
__device__ __nv_bfloat16 g_thi[(size_t)BB * MMM * DKK];
__device__ __nv_bfloat16 g_tlo[(size_t)BB * MMM * DKK];
__device__ float g_cp[(size_t)BB * 64 * MMM];      // 64 partial row-blocks per batch
__device__ float g_r[BB * NN];
__device__ float g_c[BB * MMM];
__device__ float g_weights[BB * NN];
__device__ float g_wt[BB * 3 * NN];

// ---------------- PTX helpers ----------------
__device__ __forceinline__ uint32_t smem_u32(const void* p) {
    uint32_t a;
    asm("{ .reg .u64 t; cvta.to.shared.u64 t, %1; cvt.u32.u64 %0, t; }" : "=r"(a) : "l"(p));
    return a;
}
#define LDSM4(r0, r1, r2, r3, addr) \
    asm volatile("ldmatrix.sync.aligned.m8n8.x4.shared.b16 {%0,%1,%2,%3}, [%4];" \
        : "=r"(r0), "=r"(r1), "=r"(r2), "=r"(r3) : "r"(addr))
#define MMA16816(c, a, b0, b1) \
    asm volatile("mma.sync.aligned.m16n8k16.row.col.f32.bf16.bf16.f32 " \
        "{%0,%1,%2,%3}, {%4,%5,%6,%7}, {%8,%9}, {%0,%1,%2,%3};" \
        : "+f"((c)[0]), "+f"((c)[1]), "+f"((c)[2]), "+f"((c)[3]) \
        : "r"((a)[0]), "r"((a)[1]), "r"((a)[2]), "r"((a)[3]), "r"(b0), "r"(b1))
#define CPASYNC16(saddr, gptr) \
    asm volatile("cp.async.cg.shared.global [%0], [%1], 16;" :: "r"(saddr), "l"(gptr))
#define CP_COMMIT() asm volatile("cp.async.commit_group;" ::: "memory")
#define CP_WAIT1()  asm volatile("cp.async.wait_group 1;" ::: "memory")
#define CP_WAIT0()  asm volatile("cp.async.wait_group 0;" ::: "memory")

__device__ __forceinline__ uint32_t sw128(uint32_t off) {
    return off ^ ((off >> 3) & 0x70);
}
__device__ __forceinline__ void stg_evl8(float* p, float4 v0, float4 v1) {
    asm volatile("st.global.L2::evict_last.v8.b32 [%0], {%1,%2,%3,%4,%5,%6,%7,%8};"
                 :: "l"(p),
                    "r"(__float_as_uint(v0.x)), "r"(__float_as_uint(v0.y)),
                    "r"(__float_as_uint(v0.z)), "r"(__float_as_uint(v0.w)),
                    "r"(__float_as_uint(v1.x)), "r"(__float_as_uint(v1.y)),
                    "r"(__float_as_uint(v1.z)), "r"(__float_as_uint(v1.w)) : "memory");
}

// ---------------- transpose + hi/lo bf16 split (also zeroes g_c) ----------------
__global__ __launch_bounds__(256) void convert_kernel(const float* __restrict__ srcE,
                                                      const float* __restrict__ tgtE) {
    __shared__ float s[32][33];
    const int z = blockIdx.z;
    const int bb = z & 15;
    const float* in = (z < 16) ? srcE : tgtE;
    __nv_bfloat16* hi = (z < 16) ? g_shi : g_thi;
    __nv_bfloat16* lo = (z < 16) ? g_slo : g_tlo;
    const int tid = threadIdx.x;

    if (blockIdx.y == 0 && z == 0) {
        int i = blockIdx.x * 256 + tid;      // 0..8191
        g_c[i] = 0.0f;
        g_c[i + 8192] = 0.0f;
    }

    const int tx = tid & 31, ty = tid >> 5;
    const int n = blockIdx.x * 32 + tx;
    const int d0 = blockIdx.y * 32;
#pragma unroll
    for (int j = 0; j < 4; j++)
        s[ty + 8 * j][tx] = in[((size_t)bb * DKK + d0 + ty + 8 * j) * NN + n];
    __syncthreads();
#pragma unroll
    for (int q = 0; q < 2; q++) {
        int p = tid + q * 256;
        int nl = p >> 4;
        int d = (p & 15) * 2;
        int nn = blockIdx.x * 32 + nl;
        float v0 = s[d][nl], v1 = s[d + 1][nl];
        __nv_bfloat16 h0 = __float2bfloat16(v0), h1 = __float2bfloat16(v1);
        float r0 = v0 - __bfloat162float(h0), r1 = v1 - __bfloat162float(h1);
        size_t o = ((size_t)bb * NN + nn) * DKK + d0 + d;
        *(__nv_bfloat162*)(hi + o) = __nv_bfloat162(h0, h1);
        *(__nv_bfloat162*)(lo + o) = __nv_bfloat162(__float2bfloat16(r0), __float2bfloat16(r1));
    }
}

// ---------------- bf16-split GEMM: 64x128 CTA tile, 256 thr, 2 CTAs/SM ----------------
#define STG2_B 49152

__global__ __launch_bounds__(256, 2) void gemm_mma(const float* __restrict__ temp) {
    extern __shared__ char sm_[];
    const uint32_t sb = smem_u32(sm_);
    const int tid = threadIdx.x, wid = tid >> 5, lane = tid & 31;
    const int mt = blockIdx.x, nt = blockIdx.y, bb = blockIdx.z;
    const int warp_m = wid & 1;
    const int warp_n = wid >> 1;

    const __nv_bfloat16* Ah = g_shi + ((size_t)bb * NN + nt * 64) * DKK;
    const __nv_bfloat16* Al = g_slo + ((size_t)bb * NN + nt * 64) * DKK;
    const __nv_bfloat16* Bh = g_thi + ((size_t)bb * MMM + mt * 128) * DKK;
    const __nv_bfloat16* Bl = g_tlo + ((size_t)bb * MMM + mt * 128) * DKK;

    auto stage_load = [&](int kc, int s) {
#pragma unroll
        for (int i = 0; i < 12; i++) {
            int q = tid + i * 256;
            const __nv_bfloat16* base;
            uint32_t moff;
            int row;
            if (q < 512)       { base = Ah; moff = 0;     row = q >> 3; }
            else if (q < 1024) { base = Al; moff = 8192;  row = (q - 512) >> 3; }
            else if (q < 2048) { base = Bh; moff = 16384; row = (q - 1024) >> 3; }
            else               { base = Bl; moff = 32768; row = (q - 2048) >> 3; }
            int c = q & 7;
            uint32_t saddr = sb + (uint32_t)s * STG2_B + moff + sw128(row * 128 + c * 16);
            const char* g = (const char*)(base + (size_t)row * DKK + kc * 64 + c * 8);
            CPASYNC16(saddr, g);
        }
        CP_COMMIT();
    };

    float acc[2][4][4];
#pragma unroll
    for (int i = 0; i < 2; i++)
#pragma unroll
        for (int j = 0; j < 4; j++)
#pragma unroll
            for (int k = 0; k < 4; k++) acc[i][j][k] = 0.0f;

    stage_load(0, 0);
    stage_load(1, 1);

    for (int kc = 0; kc < 8; kc++) {
        const int s = kc & 1;
        if (kc + 1 < 8) { CP_WAIT1(); }
        else            { CP_WAIT0(); }
        __syncthreads();

        const uint32_t stg = sb + (uint32_t)s * STG2_B;

#pragma unroll
        for (int h = 0; h < 4; h++) {
            uint32_t ah[2][4], al[2][4], bh[2][4], bl[2][4];
#pragma unroll
            for (int mf = 0; mf < 2; mf++) {
                uint32_t off = (uint32_t)((warp_m * 32 + mf * 16 + (lane & 15)) * 128
                              + h * 32 + (lane >> 4) * 16);
                uint32_t ad = stg + sw128(off);
                LDSM4(ah[mf][0], ah[mf][1], ah[mf][2], ah[mf][3], ad);
                LDSM4(al[mf][0], al[mf][1], al[mf][2], al[mf][3], ad + 8192);
            }
#pragma unroll
            for (int np = 0; np < 2; np++) {
                uint32_t off = (uint32_t)((warp_n * 32 + np * 16 + ((lane >> 4) & 1) * 8 + (lane & 7)) * 128
                              + h * 32 + ((lane >> 3) & 1) * 16);
                uint32_t bd = stg + 16384 + sw128(off);
                LDSM4(bh[np][0], bh[np][1], bh[np][2], bh[np][3], bd);
                LDSM4(bl[np][0], bl[np][1], bl[np][2], bl[np][3], bd + 16384);
            }
#pragma unroll
            for (int mf = 0; mf < 2; mf++)
#pragma unroll
                for (int n8 = 0; n8 < 4; n8++) {
                    const int np = n8 >> 1, hf = (n8 & 1) * 2;
                    MMA16816(acc[mf][n8], ah[mf], bh[np][hf], bh[np][hf + 1]);
                }
#pragma unroll
            for (int mf = 0; mf < 2; mf++)
#pragma unroll
                for (int n8 = 0; n8 < 4; n8++) {
                    const int np = n8 >> 1, hf = (n8 & 1) * 2;
                    MMA16816(acc[mf][n8], ah[mf], bl[np][hf], bl[np][hf + 1]);
                }
#pragma unroll
            for (int mf = 0; mf < 2; mf++)
#pragma unroll
                for (int n8 = 0; n8 < 4; n8++) {
                    const int np = n8 >> 1, hf = (n8 & 1) * 2;
                    MMA16816(acc[mf][n8], al[mf], bh[np][hf], bh[np][hf + 1]);
                }
        }
        __syncthreads();
        if (kc + 2 < 8) stage_load(kc + 2, s);
    }

    float* smF = (float*)sm_;
#pragma unroll
    for (int mf = 0; mf < 2; mf++)
#pragma unroll
        for (int n8 = 0; n8 < 4; n8++) {
            int r0 = warp_m * 32 + mf * 16 + (lane >> 2);
            int col = warp_n * 32 + n8 * 8 + (lane & 3) * 2;
            *(float2*)(smF + r0 * 132 + col)       = make_float2(acc[mf][n8][0], acc[mf][n8][1]);
            *(float2*)(smF + (r0 + 8) * 132 + col) = make_float2(acc[mf][n8][2], acc[mf][n8][3]);
        }
    __syncthreads();

    const float alpha = rsqrtf((float)DKK) / temp[bb];
    float* C = g_scores + (size_t)bb * NN * MMM + (size_t)(nt * 64) * MMM + mt * 128;
#pragma unroll
    for (int i = 0; i < 4; i++) {
        int idx = tid + i * 256;
        int row = idx >> 4, c8 = idx & 15;
        const float* sp = smF + row * 132 + c8 * 8;
        float4 v0 = *(const float4*)sp;
        float4 v1 = *(const float4*)(sp + 4);
        v0.x *= alpha; v0.y *= alpha; v0.z *= alpha; v0.w *= alpha;
        v1.x *= alpha; v1.y *= alpha; v1.z *= alpha; v1.w *= alpha;
        stg_evl8(C + (size_t)row * MMM + c8 * 8, v0, v1);
    }
}

// ---------------- row pass: 512 threads, 16 rows/block ----------------
// dynamic smem: s_aff[16][1024] (64KB) + s_c[1024] (4KB)
__global__ __launch_bounds__(512) void row_kernel() {
    extern __shared__ float sm_row[];
    float* s_aff = sm_row;                 // 16 * 1024
    float* s_c   = sm_row + 16 * 1024;     // 1024
    const int tid  = threadIdx.x;
    const int w    = tid >> 5;             // 0..15
    const int lane = tid & 31;
    const int gw   = blockIdx.x * 16 + w;
    const int bb   = gw >> 10;
    const uint32_t sb_aff = smem_u32(s_aff);
    const uint32_t sb_c   = smem_u32(s_c);

    if (tid < 256)
        CPASYNC16(sb_c + tid * 16, (const char*)(g_c + bb * MMM + tid * 4));
    const float* affbase = g_scores + (size_t)(blockIdx.x * 16) * MMM;
#pragma unroll
    for (int i = 0; i < 8; i++) {
        int q = tid + i * 512;             // 0..4095; row = q>>8, chunk = q&255
        CPASYNC16(sb_aff + q * 16, (const char*)(affbase + (size_t)(q >> 8) * MMM + (q & 255) * 4));
    }
    CP_COMMIT();
    CP_WAIT0();
    __syncthreads();

    float x[32];
    float mx = 0.0f;
    float* arow = s_aff + w * 1024;
#pragma unroll
    for (int i = 0; i < 8; i++) {
        int off = i * 128 + lane * 4;
        float4 a = *(const float4*)(arow + off);
        float4 cc = *(const float4*)(s_c + off);
        x[4 * i]     = a.x - cc.x;
        x[4 * i + 1] = a.y - cc.y;
        x[4 * i + 2] = a.z - cc.z;
        x[4 * i + 3] = a.w - cc.w;
        mx = fmaxf(mx, fmaxf(fmaxf(x[4 * i], x[4 * i + 1]), fmaxf(x[4 * i + 2], x[4 * i + 3])));
    }
#pragma unroll
    for (int o = 16; o > 0; o >>= 1) mx = fmaxf(mx, __shfl_xor_sync(0xffffffffu, mx, o));

    float s = 0.0f;
#pragma unroll
    for (int i = 0; i < 32; i++) { x[i] = __expf(x[i] - mx); s += x[i]; }
#pragma unroll
    for (int o = 16; o > 0; o >>= 1) s += __shfl_xor_sync(0xffffffffu, s, o);
    s += __expf(-mx);

    const float r = mx + logf(s);
    if (lane == 0) g_r[gw] = r;
    const float scale = __expf(mx - r);

    __syncthreads();
#pragma unroll
    for (int i = 0; i < 8; i++) {
        int off = i * 128 + lane * 4;
        float4 e;
        e.x = x[4 * i] * scale;     e.y = x[4 * i + 1] * scale;
        e.z = x[4 * i + 2] * scale; e.w = x[4 * i + 3] * scale;
        *(float4*)(arow + off) = e;
    }
    __syncthreads();

    if (tid < 256) {
        float4 acc = *(const float4*)(s_aff + tid * 4);
#pragma unroll
        for (int ww = 1; ww < 16; ww++) {
            float4 v = *(const float4*)(s_aff + ww * 1024 + tid * 4);
            acc.x += v.x; acc.y += v.y; acc.z += v.z; acc.w += v.w;
        }
        const int rb = blockIdx.x & 63;
        __stcs((float4*)(g_cp + ((size_t)(bb * 64 + rb)) * 1024 + tid * 4), acc);
    }
}

// ---------------- column reduce: coalesced float4, 64 rows ----------------
// grid = 256: b = blk>>4, column block of 64. Block: 16 quads x 16 groups of 4 rows.
__global__ __launch_bounds__(256) void colreduce_kernel() {
    __shared__ float4 sred[256];
    const int tid = threadIdx.x;
    const int q   = tid & 15;          // column quad within 64-col block
    const int g   = tid >> 4;          // row-group 0..15 (4 rows each)
    const int b   = blockIdx.x >> 4;
    const int col0 = (blockIdx.x & 15) * 64 + q * 4;
    const float* cp = g_cp + (size_t)b * 64 * 1024 + (size_t)(g * 4) * 1024 + col0;

    float4 S = make_float4(0.f, 0.f, 0.f, 0.f);
#pragma unroll
    for (int rb = 0; rb < 4; rb++) {
        float4 v = __ldcs((const float4*)(cp + (size_t)rb * 1024));
        S.x += v.x; S.y += v.y; S.z += v.z; S.w += v.w;
    }
    sred[tid] = S;
    __syncthreads();
    if (g == 0) {
#pragma unroll
        for (int j = 1; j < 16; j++) {
            float4 v = sred[q + 16 * j];
            S.x += v.x; S.y += v.y; S.z += v.z; S.w += v.w;
        }
        float* cdst = g_c + b * MMM + col0;
        float4 co = *(const float4*)cdst;
        float4 cn;
        cn.x = co.x + logf(S.x + __expf(-co.x));
        cn.y = co.y + logf(S.y + __expf(-co.y));
        cn.z = co.z + logf(S.z + __expf(-co.z));
        cn.w = co.w + logf(S.w + __expf(-co.w));
        *(float4*)cdst = cn;
    }
}

// ---------------- final: perm_norm, weights, weighted_tgt ----------------
__global__ __launch_bounds__(256) void final_kernel(const float* __restrict__ tgt,
                                                    float* __restrict__ out_pn) {
    const int gw   = (blockIdx.x * 256 + threadIdx.x) >> 5;
    const int lane = threadIdx.x & 31;
    const int bb   = gw >> 10;
    const int n    = gw & 1023;
    const float* aff = g_scores + (size_t)gw * MMM;
    const float* c   = g_c + bb * MMM;
    const float r    = g_r[gw];

    float p[32];
    float sum = 0.0f;
#pragma unroll
    for (int i = 0; i < 8; i++) {
        int off = i * 128 + lane * 4;
        float4 a = *(const float4*)(aff + off);
        float4 cc = *(const float4*)(c + off);
        float p0 = __expf(a.x - cc.x - r), p1 = __expf(a.y - cc.y - r);
        float p2 = __expf(a.z - cc.z - r), p3 = __expf(a.w - cc.w - r);
        p[4 * i] = p0; p[4 * i + 1] = p1; p[4 * i + 2] = p2; p[4 * i + 3] = p3;
        sum += p0 + p1 + p2 + p3;
    }
#pragma unroll
    for (int o = 16; o > 0; o >>= 1) sum += __shfl_xor_sync(0xffffffffu, sum, o);

    const float inv = 1.0f / (sum + 1e-8f);
    const float* t0 = tgt + (size_t)bb * 3 * MMM;
    float w0 = 0.0f, w1 = 0.0f, w2 = 0.0f;
    float* outrow = out_pn + (size_t)gw * MMM;
#pragma unroll
    for (int i = 0; i < 8; i++) {
        int off = i * 128 + lane * 4;
        float4 q;
        q.x = p[4 * i] * inv; q.y = p[4 * i + 1] * inv;
        q.z = p[4 * i + 2] * inv; q.w = p[4 * i + 3] * inv;
        __stcs((float4*)(outrow + off), q);
        float4 ta = *(const float4*)(t0 + off);
        float4 tb = *(const float4*)(t0 + MMM + off);
        float4 tc = *(const float4*)(t0 + 2 * MMM + off);
        w0 += q.x * ta.x + q.y * ta.y + q.z * ta.z + q.w * ta.w;
        w1 += q.x * tb.x + q.y * tb.y + q.z * tb.z + q.w * tb.w;
        w2 += q.x * tc.x + q.y * tc.y + q.z * tc.z + q.w * tc.w;
    }
#pragma unroll
    for (int o = 16; o > 0; o >>= 1) {
        w0 += __shfl_xor_sync(0xffffffffu, w0, o);
        w1 += __shfl_xor_sync(0xffffffffu, w1, o);
        w2 += __shfl_xor_sync(0xffffffffu, w2, o);
    }
    if (lane == 0) {
        g_weights[gw] = sum;
        g_wt[(size_t)bb * 3 * NN + n]          = w0;
        g_wt[(size_t)bb * 3 * NN + NN + n]     = w1;
        g_wt[(size_t)bb * 3 * NN + 2 * NN + n] = w2;
    }
}

// ---------------- per-batch Procrustes (double accumulation, fp32 3x3 SVD) ----------------
__device__ double block_reduce_d(double v, double* sred, int tid) {
    sred[tid] = v; __syncthreads();
    for (int s = 128; s > 0; s >>= 1) {
        if (tid < s) sred[tid] += sred[tid + s];
        __syncthreads();
    }
    double r = sred[0]; __syncthreads();
    return r;
}

__global__ __launch_bounds__(256) void procrustes_kernel(const float* __restrict__ src,
                                                         float* __restrict__ out) {
    const int bb = blockIdx.x, tid = threadIdx.x;
    __shared__ double sred[256];
    __shared__ double bc[16];

    const float* w  = g_weights + bb * NN;
    const float* wt = g_wt + (size_t)bb * 3 * NN;
    const float* sp = src + (size_t)bb * 3 * NN;

    double lv = 0.0;
    for (int n = tid; n < NN; n += 256) lv += (double)w[n];
    double wsum = block_reduce_d(lv, sred, tid);
    double denom = wsum + 1e-8;

    double acc[6] = {0, 0, 0, 0, 0, 0};
    for (int n = tid; n < NN; n += 256) {
        double wn = (double)w[n] / denom;
        acc[0] += (double)sp[n] * wn;
        acc[1] += (double)sp[NN + n] * wn;
        acc[2] += (double)sp[2 * NN + n] * wn;
        acc[3] += (double)wt[n] * wn;
        acc[4] += (double)wt[NN + n] * wn;
        acc[5] += (double)wt[2 * NN + n] * wn;
    }
    for (int q = 0; q < 6; q++) {
        double r = block_reduce_d(acc[q], sred, tid);
        if (tid == 0) bc[q] = r;
    }
    __syncthreads();
    double scent[3] = {bc[0], bc[1], bc[2]};
    double tcent[3] = {bc[3], bc[4], bc[5]};

    double h[9] = {0, 0, 0, 0, 0, 0, 0, 0, 0};
    for (int n = tid; n < NN; n += 256) {
        double wn = (double)w[n] / denom;
        double si[3] = {(double)sp[n] - scent[0],
                        (double)sp[NN + n] - scent[1],
                        (double)sp[2 * NN + n] - scent[2]};
        double tj[3] = {((double)wt[n] - tcent[0]) * wn,
                        ((double)wt[NN + n] - tcent[1]) * wn,
                        ((double)wt[2 * NN + n] - tcent[2]) * wn};
#pragma unroll
        for (int i = 0; i < 3; i++)
#pragma unroll
            for (int j = 0; j < 3; j++) h[i * 3 + j] += si[i] * tj[j];
    }
    for (int q = 0; q < 9; q++) {
        double r = block_reduce_d(h[q], sred, tid);
        if (tid == 0) bc[q] = r;
    }
    __syncthreads();

    if (tid == 0) {
        float H[3][3];
        for (int i = 0; i < 3; i++)
            for (int j = 0; j < 3; j++) H[i][j] = (float)bc[i * 3 + j];

        float A[3][3];
        for (int i = 0; i < 3; i++)
            for (int j = 0; j < 3; j++)
                A[i][j] = H[0][i] * H[0][j] + H[1][i] * H[1][j] + H[2][i] * H[2][j];
        float V[3][3] = {{1, 0, 0}, {0, 1, 0}, {0, 0, 1}};
#pragma unroll 1
        for (int sweep = 0; sweep < 18; sweep++) {
            int r3 = sweep % 3;
            int p = (r3 == 2) ? 1 : 0;
            int q = (r3 == 0) ? 1 : 2;
            float apq = A[p][q];
            if (fabsf(apq) < 1e-30f) continue;
            float theta = (A[q][q] - A[p][p]) / (2.0f * apq);
            float tt = copysignf(1.0f, theta) / (fabsf(theta) + sqrtf(theta * theta + 1.0f));
            float cc = rsqrtf(tt * tt + 1.0f);
            float ssn = tt * cc;
            for (int k = 0; k < 3; k++) {
                float akp = A[k][p], akq = A[k][q];
                A[k][p] = cc * akp - ssn * akq;
                A[k][q] = ssn * akp + cc * akq;
            }
            for (int k = 0; k < 3; k++) {
                float apk = A[p][k], aqk = A[q][k];
                A[p][k] = cc * apk - ssn * aqk;
                A[q][k] = ssn * apk + cc * aqk;
            }
            for (int k = 0; k < 3; k++) {
                float vkp = V[k][p], vkq = V[k][q];
                V[k][p] = cc * vkp - ssn * vkq;
                V[k][q] = ssn * vkp + cc * vkq;
            }
        }
        float ev[3] = {A[0][0], A[1][1], A[2][2]};
        int idx[3] = {0, 1, 2};
        if (ev[idx[0]] < ev[idx[1]]) { int t2 = idx[0]; idx[0] = idx[1]; idx[1] = t2; }
        if (ev[idx[0]] < ev[idx[2]]) { int t2 = idx[0]; idx[0] = idx[2]; idx[2] = t2; }
        if (ev[idx[1]] < ev[idx[2]]) { int t2 = idx[1]; idx[1] = idx[2]; idx[2] = t2; }

        float Vs[3][3], U[3][3];
        for (int k = 0; k < 3; k++) {
            int c = idx[k];
            float sv = sqrtf(fmaxf(ev[c], 0.0f));
            float invs = (sv > 1e-20f) ? 1.0f / sv : 0.0f;
            for (int i = 0; i < 3; i++) Vs[i][k] = V[i][c];
            for (int i = 0; i < 3; i++)
                U[i][k] = (H[i][0] * V[0][c] + H[i][1] * V[1][c] + H[i][2] * V[2][c]) * invs;
        }
        float detH = H[0][0] * (H[1][1] * H[2][2] - H[1][2] * H[2][1])
                   - H[0][1] * (H[1][0] * H[2][2] - H[1][2] * H[2][0])
                   + H[0][2] * (H[1][0] * H[2][1] - H[1][1] * H[2][0]);
        float dsg = (detH >= 0.0f) ? 1.0f : -1.0f;
        float R[3][3];
        for (int i = 0; i < 3; i++)
            for (int j = 0; j < 3; j++)
                R[i][j] = Vs[i][0] * U[j][0] + Vs[i][1] * U[j][1] + dsg * Vs[i][2] * U[j][2];
        float tv[3];
        for (int i = 0; i < 3; i++)
            tv[i] = -(R[i][0] * (float)scent[0] + R[i][1] * (float)scent[1]
                      + R[i][2] * (float)scent[2]) + (float)tcent[i];

        for (int i = 0; i < 3; i++)
            for (int j = 0; j < 3; j++)
                out[bb * 9 + i * 3 + j] = R[i][j];
        for (int i = 0; i < 3; i++)
            out[BB * 9 + bb * 3 + i] = tv[i];
    }
}

// ---------------- launch ----------------
extern "C" void kernel_launch(void* const* d_in, const int* in_sizes, int n_in,
                              void* d_out, int out_size) {
    const float* src_emb = (const float*)d_in[0];
    const float* tgt_emb = (const float*)d_in[1];
    const float* src     = (const float*)d_in[2];
    const float* tgt     = (const float*)d_in[3];
    const float* temp    = (const float*)d_in[4];
    float* out = (float*)d_out;
    float* out_pn = out + BB * 9 + BB * 3;

    convert_kernel<<<dim3(NN / 32, DKK / 32, 2 * BB), dim3(256)>>>(src_emb, tgt_emb); // 0

    const int gemm_smem = 2 * STG2_B;
    cudaFuncSetAttribute(gemm_mma, cudaFuncAttributeMaxDynamicSharedMemorySize, gemm_smem);
    gemm_mma<<<dim3(MMM / 128, NN / 64, BB), 256, gemm_smem>>>(temp);                 // 1

    const int row_smem = (16 * 1024 + 1024) * 4;   // 68 KB
    cudaFuncSetAttribute(row_kernel, cudaFuncAttributeMaxDynamicSharedMemorySize, row_smem);
    for (int it = 0; it < 5; it++) {
        row_kernel<<<(BB * NN) / 16, 512, row_smem>>>();                              // 2,4,...
        colreduce_kernel<<<256, 256>>>();                                             // 3 -> profiled
    }
    final_kernel<<<(BB * NN) / 8, 256>>>(tgt, out_pn);
    procrustes_kernel<<<BB, 256>>>(src, out);
}

// round 14
// speedup vs baseline: 1.0250x; 1.0250x over previous
#include <cuda_runtime.h>
#include <cuda_bf16.h>
#include <math.h>
#include <stdint.h>

#define BB 16
#define DKK 512
#define NN 1024
#define MMM 1024

// ---------------- scratch (device globals) ----------------
__device__ float g_scores[(size_t)BB * NN * MMM];
__device__ __nv_bfloat16 g_shi[(size_t)BB * NN * DKK];
__device__ __nv_bfloat16 g_slo[(size_t)BB * NN * DKK];
__device__ __nv_bfloat16 g_thi[(size_t)BB * MMM * DKK];
__device__ __nv_bfloat16 g_tlo[(size_t)BB * MMM * DKK];
__device__ float g_cp[(size_t)BB * 128 * MMM];
__device__ float g_r[BB * NN];
__device__ float g_c[BB * MMM];
__device__ float g_weights[BB * NN];
__device__ float g_wt[BB * 3 * NN];

// ---------------- PTX helpers ----------------
__device__ __forceinline__ uint32_t smem_u32(const void* p) {
    uint32_t a;
    asm("{ .reg .u64 t; cvta.to.shared.u64 t, %1; cvt.u32.u64 %0, t; }" : "=r"(a) : "l"(p));
    return a;
}
#define LDSM4(r0, r1, r2, r3, addr) \
    asm volatile("ldmatrix.sync.aligned.m8n8.x4.shared.b16 {%0,%1,%2,%3}, [%4];" \
        : "=r"(r0), "=r"(r1), "=r"(r2), "=r"(r3) : "r"(addr))
#define MMA16816(c, a, b0, b1) \
    asm volatile("mma.sync.aligned.m16n8k16.row.col.f32.bf16.bf16.f32 " \
        "{%0,%1,%2,%3}, {%4,%5,%6,%7}, {%8,%9}, {%0,%1,%2,%3};" \
        : "+f"((c)[0]), "+f"((c)[1]), "+f"((c)[2]), "+f"((c)[3]) \
        : "r"((a)[0]), "r"((a)[1]), "r"((a)[2]), "r"((a)[3]), "r"(b0), "r"(b1))
#define CPASYNC16(saddr, gptr) \
    asm volatile("cp.async.cg.shared.global [%0], [%1], 16;" :: "r"(saddr), "l"(gptr))
#define CP_COMMIT() asm volatile("cp.async.commit_group;" ::: "memory")
#define CP_WAIT1()  asm volatile("cp.async.wait_group 1;" ::: "memory")
#define CP_WAIT0()  asm volatile("cp.async.wait_group 0;" ::: "memory")

__device__ __forceinline__ uint32_t sw128(uint32_t off) {
    return off ^ ((off >> 3) & 0x70);
}
__device__ __forceinline__ void stg_evl8(float* p, float4 v0, float4 v1) {
    asm volatile("st.global.L2::evict_last.v8.b32 [%0], {%1,%2,%3,%4,%5,%6,%7,%8};"
                 :: "l"(p),
                    "r"(__float_as_uint(v0.x)), "r"(__float_as_uint(v0.y)),
                    "r"(__float_as_uint(v0.z)), "r"(__float_as_uint(v0.w)),
                    "r"(__float_as_uint(v1.x)), "r"(__float_as_uint(v1.y)),
                    "r"(__float_as_uint(v1.z)), "r"(__float_as_uint(v1.w)) : "memory");
}

// ---------------- transpose + hi/lo bf16 split (also zeroes g_c) ----------------
__global__ __launch_bounds__(256) void convert_kernel(const float* __restrict__ srcE,
                                                      const float* __restrict__ tgtE) {
    __shared__ float s[32][33];
    const int z = blockIdx.z;
    const int bb = z & 15;
    const float* in = (z < 16) ? srcE : tgtE;
    __nv_bfloat16* hi = (z < 16) ? g_shi : g_thi;
    __nv_bfloat16* lo = (z < 16) ? g_slo : g_tlo;
    const int tid = threadIdx.x;

    if (blockIdx.y == 0 && z == 0) {
        int i = blockIdx.x * 256 + tid;      // 0..8191
        g_c[i] = 0.0f;
        g_c[i + 8192] = 0.0f;
    }

    const int tx = tid & 31, ty = tid >> 5;
    const int n = blockIdx.x * 32 + tx;
    const int d0 = blockIdx.y * 32;
#pragma unroll
    for (int j = 0; j < 4; j++)
        s[ty + 8 * j][tx] = in[((size_t)bb * DKK + d0 + ty + 8 * j) * NN + n];
    __syncthreads();
#pragma unroll
    for (int q = 0; q < 2; q++) {
        int p = tid + q * 256;
        int nl = p >> 4;
        int d = (p & 15) * 2;
        int nn = blockIdx.x * 32 + nl;
        float v0 = s[d][nl], v1 = s[d + 1][nl];
        __nv_bfloat16 h0 = __float2bfloat16(v0), h1 = __float2bfloat16(v1);
        float r0 = v0 - __bfloat162float(h0), r1 = v1 - __bfloat162float(h1);
        size_t o = ((size_t)bb * NN + nn) * DKK + d0 + d;
        *(__nv_bfloat162*)(hi + o) = __nv_bfloat162(h0, h1);
        *(__nv_bfloat162*)(lo + o) = __nv_bfloat162(__float2bfloat16(r0), __float2bfloat16(r1));
    }
}

// ---------------- bf16-split GEMM: 64x128 CTA tile, 256 thr, 2 CTAs/SM ----------------
#define STG2_B 49152

__global__ __launch_bounds__(256, 2) void gemm_mma(const float* __restrict__ temp) {
    extern __shared__ char sm_[];
    const uint32_t sb = smem_u32(sm_);
    const int tid = threadIdx.x, wid = tid >> 5, lane = tid & 31;
    const int mt = blockIdx.x, nt = blockIdx.y, bb = blockIdx.z;
    const int warp_m = wid & 1;
    const int warp_n = wid >> 1;

    const __nv_bfloat16* Ah = g_shi + ((size_t)bb * NN + nt * 64) * DKK;
    const __nv_bfloat16* Al = g_slo + ((size_t)bb * NN + nt * 64) * DKK;
    const __nv_bfloat16* Bh = g_thi + ((size_t)bb * MMM + mt * 128) * DKK;
    const __nv_bfloat16* Bl = g_tlo + ((size_t)bb * MMM + mt * 128) * DKK;

    auto stage_load = [&](int kc, int s) {
#pragma unroll
        for (int i = 0; i < 12; i++) {
            int q = tid + i * 256;
            const __nv_bfloat16* base;
            uint32_t moff;
            int row;
            if (q < 512)       { base = Ah; moff = 0;     row = q >> 3; }
            else if (q < 1024) { base = Al; moff = 8192;  row = (q - 512) >> 3; }
            else if (q < 2048) { base = Bh; moff = 16384; row = (q - 1024) >> 3; }
            else               { base = Bl; moff = 32768; row = (q - 2048) >> 3; }
            int c = q & 7;
            uint32_t saddr = sb + (uint32_t)s * STG2_B + moff + sw128(row * 128 + c * 16);
            const char* g = (const char*)(base + (size_t)row * DKK + kc * 64 + c * 8);
            CPASYNC16(saddr, g);
        }
        CP_COMMIT();
    };

    float acc[2][4][4];
#pragma unroll
    for (int i = 0; i < 2; i++)
#pragma unroll
        for (int j = 0; j < 4; j++)
#pragma unroll
            for (int k = 0; k < 4; k++) acc[i][j][k] = 0.0f;

    stage_load(0, 0);
    stage_load(1, 1);

    for (int kc = 0; kc < 8; kc++) {
        const int s = kc & 1;
        if (kc + 1 < 8) { CP_WAIT1(); }
        else            { CP_WAIT0(); }
        __syncthreads();

        const uint32_t stg = sb + (uint32_t)s * STG2_B;

#pragma unroll
        for (int h = 0; h < 4; h++) {
            uint32_t ah[2][4], al[2][4], bh[2][4], bl[2][4];
#pragma unroll
            for (int mf = 0; mf < 2; mf++) {
                uint32_t off = (uint32_t)((warp_m * 32 + mf * 16 + (lane & 15)) * 128
                              + h * 32 + (lane >> 4) * 16);
                uint32_t ad = stg + sw128(off);
                LDSM4(ah[mf][0], ah[mf][1], ah[mf][2], ah[mf][3], ad);
                LDSM4(al[mf][0], al[mf][1], al[mf][2], al[mf][3], ad + 8192);
            }
#pragma unroll
            for (int np = 0; np < 2; np++) {
                uint32_t off = (uint32_t)((warp_n * 32 + np * 16 + ((lane >> 4) & 1) * 8 + (lane & 7)) * 128
                              + h * 32 + ((lane >> 3) & 1) * 16);
                uint32_t bd = stg + 16384 + sw128(off);
                LDSM4(bh[np][0], bh[np][1], bh[np][2], bh[np][3], bd);
                LDSM4(bl[np][0], bl[np][1], bl[np][2], bl[np][3], bd + 16384);
            }
#pragma unroll
            for (int mf = 0; mf < 2; mf++)
#pragma unroll
                for (int n8 = 0; n8 < 4; n8++) {
                    const int np = n8 >> 1, hf = (n8 & 1) * 2;
                    MMA16816(acc[mf][n8], ah[mf], bh[np][hf], bh[np][hf + 1]);
                }
#pragma unroll
            for (int mf = 0; mf < 2; mf++)
#pragma unroll
                for (int n8 = 0; n8 < 4; n8++) {
                    const int np = n8 >> 1, hf = (n8 & 1) * 2;
                    MMA16816(acc[mf][n8], ah[mf], bl[np][hf], bl[np][hf + 1]);
                }
#pragma unroll
            for (int mf = 0; mf < 2; mf++)
#pragma unroll
                for (int n8 = 0; n8 < 4; n8++) {
                    const int np = n8 >> 1, hf = (n8 & 1) * 2;
                    MMA16816(acc[mf][n8], al[mf], bh[np][hf], bh[np][hf + 1]);
                }
        }
        __syncthreads();
        if (kc + 2 < 8) stage_load(kc + 2, s);
    }

    float* smF = (float*)sm_;
#pragma unroll
    for (int mf = 0; mf < 2; mf++)
#pragma unroll
        for (int n8 = 0; n8 < 4; n8++) {
            int r0 = warp_m * 32 + mf * 16 + (lane >> 2);
            int col = warp_n * 32 + n8 * 8 + (lane & 3) * 2;
            *(float2*)(smF + r0 * 132 + col)       = make_float2(acc[mf][n8][0], acc[mf][n8][1]);
            *(float2*)(smF + (r0 + 8) * 132 + col) = make_float2(acc[mf][n8][2], acc[mf][n8][3]);
        }
    __syncthreads();

    const float alpha = rsqrtf((float)DKK) / temp[bb];
    float* C = g_scores + (size_t)bb * NN * MMM + (size_t)(nt * 64) * MMM + mt * 128;
#pragma unroll
    for (int i = 0; i < 4; i++) {
        int idx = tid + i * 256;
        int row = idx >> 4, c8 = idx & 15;
        const float* sp = smF + row * 132 + c8 * 8;
        float4 v0 = *(const float4*)sp;
        float4 v1 = *(const float4*)(sp + 4);
        v0.x *= alpha; v0.y *= alpha; v0.z *= alpha; v0.w *= alpha;
        v1.x *= alpha; v1.y *= alpha; v1.z *= alpha; v1.w *= alpha;
        stg_evl8(C + (size_t)row * MMM + c8 * 8, v0, v1);
    }
}

// ---------------- row pass: 256 threads, 8 rows/block (round-12 champion) ----------------
__global__ __launch_bounds__(256) void row_kernel() {
    __shared__ float s_aff[8][1024];
    __shared__ float s_c[1024];
    const int tid  = threadIdx.x;
    const int w    = tid >> 5;
    const int lane = tid & 31;
    const int gw   = blockIdx.x * 8 + w;
    const int bb   = gw >> 10;
    const uint32_t sb_aff = smem_u32(&s_aff[0][0]);
    const uint32_t sb_c   = smem_u32(&s_c[0]);

    CPASYNC16(sb_c + tid * 16, (const char*)(g_c + bb * MMM + tid * 4));
    const float* affbase = g_scores + (size_t)(blockIdx.x * 8) * MMM;
#pragma unroll
    for (int i = 0; i < 8; i++) {
        int q = tid + i * 256;
        CPASYNC16(sb_aff + q * 16, (const char*)(affbase + (size_t)(q >> 8) * MMM + (q & 255) * 4));
    }
    CP_COMMIT();
    CP_WAIT0();
    __syncthreads();

    float x[32];
    float mx = 0.0f;
#pragma unroll
    for (int i = 0; i < 8; i++) {
        int off = i * 128 + lane * 4;
        float4 a = *(const float4*)(&s_aff[w][off]);
        float4 cc = *(const float4*)(&s_c[off]);
        x[4 * i]     = a.x - cc.x;
        x[4 * i + 1] = a.y - cc.y;
        x[4 * i + 2] = a.z - cc.z;
        x[4 * i + 3] = a.w - cc.w;
        mx = fmaxf(mx, fmaxf(fmaxf(x[4 * i], x[4 * i + 1]), fmaxf(x[4 * i + 2], x[4 * i + 3])));
    }
#pragma unroll
    for (int o = 16; o > 0; o >>= 1) mx = fmaxf(mx, __shfl_xor_sync(0xffffffffu, mx, o));

    float s = 0.0f;
#pragma unroll
    for (int i = 0; i < 32; i++) { x[i] = __expf(x[i] - mx); s += x[i]; }
#pragma unroll
    for (int o = 16; o > 0; o >>= 1) s += __shfl_xor_sync(0xffffffffu, s, o);
    s += __expf(-mx);

    const float r = mx + logf(s);
    if (lane == 0) g_r[gw] = r;
    const float scale = __expf(mx - r);

    __syncthreads();
#pragma unroll
    for (int i = 0; i < 8; i++) {
        int off = i * 128 + lane * 4;
        float4 e;
        e.x = x[4 * i] * scale;     e.y = x[4 * i + 1] * scale;
        e.z = x[4 * i + 2] * scale; e.w = x[4 * i + 3] * scale;
        *(float4*)(&s_aff[w][off]) = e;
    }
    __syncthreads();

    float4 acc = *(const float4*)(&s_aff[0][tid * 4]);
#pragma unroll
    for (int ww = 1; ww < 8; ww++) {
        float4 v = *(const float4*)(&s_aff[ww][tid * 4]);
        acc.x += v.x; acc.y += v.y; acc.z += v.z; acc.w += v.w;
    }
    const int rb = blockIdx.x & 127;
    __stcs((float4*)(g_cp + ((size_t)(bb * 128 + rb)) * 1024 + tid * 4), acc);
}

// ---------------- column reduce: coalesced float4 over 128 partial rows ----------------
// grid = 256: b = blk>>4, 64-column block. Block: 16 quads x 16 row-groups of 8 rows.
__global__ __launch_bounds__(256) void colreduce_kernel() {
    __shared__ float4 sred[256];
    const int tid = threadIdx.x;
    const int q   = tid & 15;          // column quad within 64-col block
    const int g   = tid >> 4;          // row-group 0..15 (8 rows each)
    const int b   = blockIdx.x >> 4;
    const int col0 = (blockIdx.x & 15) * 64 + q * 4;
    const float* cp = g_cp + (size_t)b * 128 * 1024 + (size_t)(g * 8) * 1024 + col0;

    float4 S = make_float4(0.f, 0.f, 0.f, 0.f);
#pragma unroll
    for (int rb = 0; rb < 8; rb++) {
        float4 v = __ldcs((const float4*)(cp + (size_t)rb * 1024));
        S.x += v.x; S.y += v.y; S.z += v.z; S.w += v.w;
    }
    sred[tid] = S;
    __syncthreads();
    if (g == 0) {
#pragma unroll
        for (int j = 1; j < 16; j++) {
            float4 v = sred[q + 16 * j];
            S.x += v.x; S.y += v.y; S.z += v.z; S.w += v.w;
        }
        float* cdst = g_c + b * MMM + col0;
        float4 co = *(const float4*)cdst;
        float4 cn;
        cn.x = co.x + logf(S.x + __expf(-co.x));
        cn.y = co.y + logf(S.y + __expf(-co.y));
        cn.z = co.z + logf(S.z + __expf(-co.z));
        cn.w = co.w + logf(S.w + __expf(-co.w));
        *(float4*)cdst = cn;
    }
}

// ---------------- final: perm_norm, weights, weighted_tgt ----------------
__global__ __launch_bounds__(256) void final_kernel(const float* __restrict__ tgt,
                                                    float* __restrict__ out_pn) {
    const int gw   = (blockIdx.x * 256 + threadIdx.x) >> 5;
    const int lane = threadIdx.x & 31;
    const int bb   = gw >> 10;
    const int n    = gw & 1023;
    const float* aff = g_scores + (size_t)gw * MMM;
    const float* c   = g_c + bb * MMM;
    const float r    = g_r[gw];

    float p[32];
    float sum = 0.0f;
#pragma unroll
    for (int i = 0; i < 8; i++) {
        int off = i * 128 + lane * 4;
        float4 a = *(const float4*)(aff + off);
        float4 cc = *(const float4*)(c + off);
        float p0 = __expf(a.x - cc.x - r), p1 = __expf(a.y - cc.y - r);
        float p2 = __expf(a.z - cc.z - r), p3 = __expf(a.w - cc.w - r);
        p[4 * i] = p0; p[4 * i + 1] = p1; p[4 * i + 2] = p2; p[4 * i + 3] = p3;
        sum += p0 + p1 + p2 + p3;
    }
#pragma unroll
    for (int o = 16; o > 0; o >>= 1) sum += __shfl_xor_sync(0xffffffffu, sum, o);

    const float inv = 1.0f / (sum + 1e-8f);
    const float* t0 = tgt + (size_t)bb * 3 * MMM;
    float w0 = 0.0f, w1 = 0.0f, w2 = 0.0f;
    float* outrow = out_pn + (size_t)gw * MMM;
#pragma unroll
    for (int i = 0; i < 8; i++) {
        int off = i * 128 + lane * 4;
        float4 q;
        q.x = p[4 * i] * inv; q.y = p[4 * i + 1] * inv;
        q.z = p[4 * i + 2] * inv; q.w = p[4 * i + 3] * inv;
        __stcs((float4*)(outrow + off), q);
        float4 ta = *(const float4*)(t0 + off);
        float4 tb = *(const float4*)(t0 + MMM + off);
        float4 tc = *(const float4*)(t0 + 2 * MMM + off);
        w0 += q.x * ta.x + q.y * ta.y + q.z * ta.z + q.w * ta.w;
        w1 += q.x * tb.x + q.y * tb.y + q.z * tb.z + q.w * tb.w;
        w2 += q.x * tc.x + q.y * tc.y + q.z * tc.z + q.w * tc.w;
    }
#pragma unroll
    for (int o = 16; o > 0; o >>= 1) {
        w0 += __shfl_xor_sync(0xffffffffu, w0, o);
        w1 += __shfl_xor_sync(0xffffffffu, w1, o);
        w2 += __shfl_xor_sync(0xffffffffu, w2, o);
    }
    if (lane == 0) {
        g_weights[gw] = sum;
        g_wt[(size_t)bb * 3 * NN + n]          = w0;
        g_wt[(size_t)bb * 3 * NN + NN + n]     = w1;
        g_wt[(size_t)bb * 3 * NN + 2 * NN + n] = w2;
    }
}

// ---------------- per-batch Procrustes (double accumulation, fp32 3x3 SVD) ----------------
__device__ double block_reduce_d(double v, double* sred, int tid) {
    sred[tid] = v; __syncthreads();
    for (int s = 128; s > 0; s >>= 1) {
        if (tid < s) sred[tid] += sred[tid + s];
        __syncthreads();
    }
    double r = sred[0]; __syncthreads();
    return r;
}

__global__ __launch_bounds__(256) void procrustes_kernel(const float* __restrict__ src,
                                                         float* __restrict__ out) {
    const int bb = blockIdx.x, tid = threadIdx.x;
    __shared__ double sred[256];
    __shared__ double bc[16];

    const float* w  = g_weights + bb * NN;
    const float* wt = g_wt + (size_t)bb * 3 * NN;
    const float* sp = src + (size_t)bb * 3 * NN;

    double lv = 0.0;
    for (int n = tid; n < NN; n += 256) lv += (double)w[n];
    double wsum = block_reduce_d(lv, sred, tid);
    double denom = wsum + 1e-8;

    double acc[6] = {0, 0, 0, 0, 0, 0};
    for (int n = tid; n < NN; n += 256) {
        double wn = (double)w[n] / denom;
        acc[0] += (double)sp[n] * wn;
        acc[1] += (double)sp[NN + n] * wn;
        acc[2] += (double)sp[2 * NN + n] * wn;
        acc[3] += (double)wt[n] * wn;
        acc[4] += (double)wt[NN + n] * wn;
        acc[5] += (double)wt[2 * NN + n] * wn;
    }
    for (int q = 0; q < 6; q++) {
        double r = block_reduce_d(acc[q], sred, tid);
        if (tid == 0) bc[q] = r;
    }
    __syncthreads();
    double scent[3] = {bc[0], bc[1], bc[2]};
    double tcent[3] = {bc[3], bc[4], bc[5]};

    double h[9] = {0, 0, 0, 0, 0, 0, 0, 0, 0};
    for (int n = tid; n < NN; n += 256) {
        double wn = (double)w[n] / denom;
        double si[3] = {(double)sp[n] - scent[0],
                        (double)sp[NN + n] - scent[1],
                        (double)sp[2 * NN + n] - scent[2]};
        double tj[3] = {((double)wt[n] - tcent[0]) * wn,
                        ((double)wt[NN + n] - tcent[1]) * wn,
                        ((double)wt[2 * NN + n] - tcent[2]) * wn};
#pragma unroll
        for (int i = 0; i < 3; i++)
#pragma unroll
            for (int j = 0; j < 3; j++) h[i * 3 + j] += si[i] * tj[j];
    }
    for (int q = 0; q < 9; q++) {
        double r = block_reduce_d(h[q], sred, tid);
        if (tid == 0) bc[q] = r;
    }
    __syncthreads();

    if (tid == 0) {
        float H[3][3];
        for (int i = 0; i < 3; i++)
            for (int j = 0; j < 3; j++) H[i][j] = (float)bc[i * 3 + j];

        float A[3][3];
        for (int i = 0; i < 3; i++)
            for (int j = 0; j < 3; j++)
                A[i][j] = H[0][i] * H[0][j] + H[1][i] * H[1][j] + H[2][i] * H[2][j];
        float V[3][3] = {{1, 0, 0}, {0, 1, 0}, {0, 0, 1}};
#pragma unroll 1
        for (int sweep = 0; sweep < 18; sweep++) {
            int r3 = sweep % 3;
            int p = (r3 == 2) ? 1 : 0;
            int q = (r3 == 0) ? 1 : 2;
            float apq = A[p][q];
            if (fabsf(apq) < 1e-30f) continue;
            float theta = (A[q][q] - A[p][p]) / (2.0f * apq);
            float tt = copysignf(1.0f, theta) / (fabsf(theta) + sqrtf(theta * theta + 1.0f));
            float cc = rsqrtf(tt * tt + 1.0f);
            float ssn = tt * cc;
            for (int k = 0; k < 3; k++) {
                float akp = A[k][p], akq = A[k][q];
                A[k][p] = cc * akp - ssn * akq;
                A[k][q] = ssn * akp + cc * akq;
            }
            for (int k = 0; k < 3; k++) {
                float apk = A[p][k], aqk = A[q][k];
                A[p][k] = cc * apk - ssn * aqk;
                A[q][k] = ssn * apk + cc * aqk;
            }
            for (int k = 0; k < 3; k++) {
                float vkp = V[k][p], vkq = V[k][q];
                V[k][p] = cc * vkp - ssn * vkq;
                V[k][q] = ssn * vkp + cc * vkq;
            }
        }
        float ev[3] = {A[0][0], A[1][1], A[2][2]};
        int idx[3] = {0, 1, 2};
        if (ev[idx[0]] < ev[idx[1]]) { int t2 = idx[0]; idx[0] = idx[1]; idx[1] = t2; }
        if (ev[idx[0]] < ev[idx[2]]) { int t2 = idx[0]; idx[0] = idx[2]; idx[2] = t2; }
        if (ev[idx[1]] < ev[idx[2]]) { int t2 = idx[1]; idx[1] = idx[2]; idx[2] = t2; }

        float Vs[3][3], U[3][3];
        for (int k = 0; k < 3; k++) {
            int c = idx[k];
            float sv = sqrtf(fmaxf(ev[c], 0.0f));
            float invs = (sv > 1e-20f) ? 1.0f / sv : 0.0f;
            for (int i = 0; i < 3; i++) Vs[i][k] = V[i][c];
            for (int i = 0; i < 3; i++)
                U[i][k] = (H[i][0] * V[0][c] + H[i][1] * V[1][c] + H[i][2] * V[2][c]) * invs;
        }
        float detH = H[0][0] * (H[1][1] * H[2][2] - H[1][2] * H[2][1])
                   - H[0][1] * (H[1][0] * H[2][2] - H[1][2] * H[2][0])
                   + H[0][2] * (H[1][0] * H[2][1] - H[1][1] * H[2][0]);
        float dsg = (detH >= 0.0f) ? 1.0f : -1.0f;
        float R[3][3];
        for (int i = 0; i < 3; i++)
            for (int j = 0; j < 3; j++)
                R[i][j] = Vs[i][0] * U[j][0] + Vs[i][1] * U[j][1] + dsg * Vs[i][2] * U[j][2];
        float tv[3];
        for (int i = 0; i < 3; i++)
            tv[i] = -(R[i][0] * (float)scent[0] + R[i][1] * (float)scent[1]
                      + R[i][2] * (float)scent[2]) + (float)tcent[i];

        for (int i = 0; i < 3; i++)
            for (int j = 0; j < 3; j++)
                out[bb * 9 + i * 3 + j] = R[i][j];
        for (int i = 0; i < 3; i++)
            out[BB * 9 + bb * 3 + i] = tv[i];
    }
}

// ---------------- launch ----------------
extern "C" void kernel_launch(void* const* d_in, const int* in_sizes, int n_in,
                              void* d_out, int out_size) {
    const float* src_emb = (const float*)d_in[0];
    const float* tgt_emb = (const float*)d_in[1];
    const float* src     = (const float*)d_in[2];
    const float* tgt     = (const float*)d_in[3];
    const float* temp    = (const float*)d_in[4];
    float* out = (float*)d_out;
    float* out_pn = out + BB * 9 + BB * 3;

    convert_kernel<<<dim3(NN / 32, DKK / 32, 2 * BB), dim3(256)>>>(src_emb, tgt_emb); // 0

    const int gemm_smem = 2 * STG2_B;
    cudaFuncSetAttribute(gemm_mma, cudaFuncAttributeMaxDynamicSharedMemorySize, gemm_smem);
    gemm_mma<<<dim3(MMM / 128, NN / 64, BB), 256, gemm_smem>>>(temp);                 // 1

    for (int it = 0; it < 5; it++) {
        row_kernel<<<(BB * NN) / 8, 256>>>();                                         // 2,4,...
        colreduce_kernel<<<256, 256>>>();                                             // 3 -> profiled
    }
    final_kernel<<<(BB * NN) / 8, 256>>>(tgt, out_pn);
    procrustes_kernel<<<BB, 256>>>(src, out);
}